// round 12
// baseline (speedup 1.0000x reference)
#include <cuda_runtime.h>
#include <cuda_fp16.h>
#include <cstdint>

// Problem dims
#define HH 128
#define WD 128
#define BB 8
#define DD 512
#define M_TOTAL (HH * WD * BB)   // 131072 rows
#define X_ELEMS ((size_t)M_TOTAL * DD)
#define W_ELEMS ((size_t)DD * DD)
#define GUARD 2e-5f
#define CAP 128

// Scratch
__device__ float g_y[(size_t)M_TOTAL * DD];
__device__ __half g_x0[X_ELEMS];
__device__ __half g_x1[X_ELEMS];
__device__ __half g_w0[W_ELEMS];
__device__ __half g_w1[W_ELEMS];
__device__ int g_ecnt[HH * BB];
__device__ unsigned short g_elist[HH * BB][CAP];

// ---------------------------------------------------------------------------
// MMA / LDSM / cp.async macros
// ---------------------------------------------------------------------------
#define MMA_ZERO(d, a, b0, b1)                                               \
    asm volatile(                                                            \
        "mma.sync.aligned.m16n8k16.row.col.f32.f16.f16.f32 "                \
        "{%0,%1,%2,%3}, {%4,%5,%6,%7}, {%8,%9}, {%10,%10,%10,%10};"         \
        : "=f"((d)[0]), "=f"((d)[1]), "=f"((d)[2]), "=f"((d)[3])             \
        : "r"((a)[0]), "r"((a)[1]), "r"((a)[2]), "r"((a)[3]),                \
          "r"(b0), "r"(b1), "f"(0.0f))

#define MMA_ACC(d, a, b0, b1)                                                \
    asm volatile(                                                            \
        "mma.sync.aligned.m16n8k16.row.col.f32.f16.f16.f32 "                \
        "{%0,%1,%2,%3}, {%4,%5,%6,%7}, {%8,%9}, {%0,%1,%2,%3};"             \
        : "+f"((d)[0]), "+f"((d)[1]), "+f"((d)[2]), "+f"((d)[3])             \
        : "r"((a)[0]), "r"((a)[1]), "r"((a)[2]), "r"((a)[3]),                \
          "r"(b0), "r"(b1))

#define LDSM_X4(r, addr)                                                     \
    asm volatile(                                                            \
        "ldmatrix.sync.aligned.m8n8.x4.shared.b16 {%0,%1,%2,%3}, [%4];"     \
        : "=r"((r)[0]), "=r"((r)[1]), "=r"((r)[2]), "=r"((r)[3])             \
        : "r"(addr))

#define CP_ASYNC(dst, src)                                                   \
    asm volatile("cp.async.cg.shared.global [%0], [%1], 16;"                \
                 :: "r"(dst), "l"(src) : "memory")
#define CP_COMMIT()  asm volatile("cp.async.commit_group;" ::: "memory")
#define CP_WAIT0()   asm volatile("cp.async.wait_group 0;" ::: "memory")

// SMEM geometry (uint32 units): [row 0..127][kp 0..15] stride 20.
// 4 arrays per stage (A0, A1, W0, W1), 2 stages.
#define RST  20
#define ARR  (128 * RST)        // 2560 u32 = 10240 B
#define SSTG (4 * ARR)
#define SMEM_GEMM (2 * SSTG * 4)  // 81920 B

__device__ __forceinline__ uint32_t smem_u32(const void* p) {
    uint32_t a;
    asm("{ .reg .u64 t; cvta.to.shared.u64 t, %1; cvt.u32.u64 %0, t; }"
        : "=r"(a) : "l"(p));
    return a;
}

// ---------------------------------------------------------------------------
// Pre-split: fp32 -> fp16 hi/lo
// ---------------------------------------------------------------------------
__global__ __launch_bounds__(256) void split_kernel(
    const float* __restrict__ x, const float* __restrict__ w)
{
    const int tid = threadIdx.x;
    if (blockIdx.x == 0) {
        for (int i = tid; i < HH * BB; i += 256) g_ecnt[i] = 0;
    }
    size_t i4 = ((size_t)blockIdx.x * 256 + tid) * 4;
    const float* src;
    __half *d0, *d1;
    if (i4 < X_ELEMS) {
        src = x + i4; d0 = g_x0 + i4; d1 = g_x1 + i4;
    } else {
        i4 -= X_ELEMS;
        if (i4 >= W_ELEMS) return;
        src = w + i4; d0 = g_w0 + i4; d1 = g_w1 + i4;
    }
    float4 v = *(const float4*)src;
    const float f[4] = {v.x, v.y, v.z, v.w};
    unsigned short h[4], l[4];
#pragma unroll
    for (int j = 0; j < 4; ++j) {
        __half hh = __float2half_rn(f[j]);
        __half ll = __float2half_rn(f[j] - __half2float(hh));
        h[j] = __half_as_ushort(hh);
        l[j] = __half_as_ushort(ll);
    }
    *(uint2*)d0 = make_uint2((uint32_t)h[0] | ((uint32_t)h[1] << 16),
                             (uint32_t)h[2] | ((uint32_t)h[3] << 16));
    *(uint2*)d1 = make_uint2((uint32_t)l[0] | ((uint32_t)l[1] << 16),
                             (uint32_t)l[2] | ((uint32_t)l[3] << 16));
}

// ---------------------------------------------------------------------------
// GEMM (unchanged from R11): fp16 2-level split, 3 passes; 6-MMA fresh chain,
// FADD master. CTA 128x128, BK=32, 8 warps (2M x 4N), ldmatrix, cp.async,
// double-buffered, 2 CTAs/SM.
// ---------------------------------------------------------------------------
__global__ __launch_bounds__(256, 2) void gemm_tc_kernel(
    const float* __restrict__ bias)
{
    extern __shared__ uint32_t smem[];
    const uint32_t sb = smem_u32(smem);

    const int tid  = threadIdx.x;
    const int lane = tid & 31;
    const int wid  = tid >> 5;
    const int wm   = wid >> 2;        // 0..1
    const int wn   = wid & 3;         // 0..3

    const int m0 = blockIdx.y << 7;
    const int n0 = blockIdx.x << 7;

    const int prow  = tid >> 1;
    const int cpair = (tid & 1) << 1;
    const __half* src[4];
    src[0] = g_x0 + (size_t)(m0 + prow) * 512 + cpair * 8;
    src[1] = g_x1 + (size_t)(m0 + prow) * 512 + cpair * 8;
    src[2] = g_w0 + (size_t)(n0 + prow) * 512 + cpair * 8;
    src[3] = g_w1 + (size_t)(n0 + prow) * 512 + cpair * 8;
    const uint32_t dstb = sb + 4 * (prow * RST + cpair * 4);

    const uint32_t a_off = ((wm << 6) + (lane & 15)) * RST + ((lane >> 4) << 2);
    const uint32_t b_off = ((wn << 5) + ((lane >> 4) << 3) + (lane & 7)) * RST +
                           (((lane >> 3) & 1) << 2);

    float acc[4][4][4];
#pragma unroll
    for (int mt = 0; mt < 4; ++mt)
#pragma unroll
        for (int nt = 0; nt < 4; ++nt)
#pragma unroll
            for (int r = 0; r < 4; ++r) acc[mt][nt][r] = 0.0f;

#pragma unroll
    for (int arr = 0; arr < 4; ++arr) {
#pragma unroll
        for (int c = 0; c < 2; ++c)
            CP_ASYNC(dstb + 4 * (arr * ARR) + c * 16, src[arr] + c * 8);
    }
    CP_COMMIT();

    for (int it = 0; it < 16; ++it) {
        const uint32_t stg = (it & 1) ? (uint32_t)SSTG : 0u;

        CP_WAIT0();
        __syncthreads();

        if (it < 15) {
            const uint32_t nst = (it & 1) ? 0u : (uint32_t)SSTG;
            const int koff = (it + 1) * 32;
#pragma unroll
            for (int arr = 0; arr < 4; ++arr) {
#pragma unroll
                for (int c = 0; c < 2; ++c)
                    CP_ASYNC(dstb + 4 * (nst + arr * ARR) + c * 16,
                             src[arr] + koff + c * 8);
            }
            CP_COMMIT();
        }

        uint32_t bfr[2][2][2][4];
#pragma unroll
        for (int lvl = 0; lvl < 2; ++lvl)
#pragma unroll
            for (int ks = 0; ks < 2; ++ks)
#pragma unroll
                for (int ntp = 0; ntp < 2; ++ntp) {
                    const uint32_t addr = sb + 4 * (stg + (2 + lvl) * ARR +
                                                    b_off + ks * 8 + ntp * 320);
                    LDSM_X4(bfr[lvl][ks][ntp], addr);
                }

#pragma unroll
        for (int mt = 0; mt < 4; ++mt) {
            uint32_t af[2][2][4];
#pragma unroll
            for (int lvl = 0; lvl < 2; ++lvl)
#pragma unroll
                for (int ks = 0; ks < 2; ++ks) {
                    const uint32_t addr = sb + 4 * (stg + lvl * ARR + a_off +
                                                    ks * 8 + mt * 320);
                    LDSM_X4(af[lvl][ks], addr);
                }
#pragma unroll
            for (int nt = 0; nt < 4; ++nt) {
                const int ntp = nt >> 1, so = (nt & 1) << 1;
                float d[4];
                MMA_ZERO(d, af[1][0], bfr[0][0][ntp][so], bfr[0][0][ntp][so + 1]);
                MMA_ACC(d, af[1][1], bfr[0][1][ntp][so], bfr[0][1][ntp][so + 1]);
                MMA_ACC(d, af[0][0], bfr[1][0][ntp][so], bfr[1][0][ntp][so + 1]);
                MMA_ACC(d, af[0][1], bfr[1][1][ntp][so], bfr[1][1][ntp][so + 1]);
                MMA_ACC(d, af[0][0], bfr[0][0][ntp][so], bfr[0][0][ntp][so + 1]);
                MMA_ACC(d, af[0][1], bfr[0][1][ntp][so], bfr[0][1][ntp][so + 1]);
                acc[mt][nt][0] += d[0];
                acc[mt][nt][1] += d[1];
                acc[mt][nt][2] += d[2];
                acc[mt][nt][3] += d[3];
            }
        }
    }

    const int q = lane & 3;
    const int r = lane >> 2;
#pragma unroll
    for (int nt = 0; nt < 4; ++nt) {
        const int col = n0 + (wn << 5) + (nt << 3) + (q << 1);
        const float2 bb = *(const float2*)&bias[col];
#pragma unroll
        for (int mt = 0; mt < 4; ++mt) {
            const int rrow = m0 + (wm << 6) + (mt << 4) + r;
            float2 v0, v1;
            v0.x = acc[mt][nt][0] + bb.x;
            v0.y = acc[mt][nt][1] + bb.y;
            v1.x = acc[mt][nt][2] + bb.x;
            v1.y = acc[mt][nt][3] + bb.y;
            *(float2*)&g_y[(size_t)rrow * 512 + col]       = v0;
            *(float2*)&g_y[(size_t)(rrow + 8) * 512 + col] = v1;
        }
    }
}

// ---------------------------------------------------------------------------
// Scan v2: smem-staged single-DRAM-read bidirectional LIF scan + flagging.
// One block per (h, b, e-half): stages y[128w][256e] (128KB) in smem.
// ---------------------------------------------------------------------------
#define SCAN_SMEM (128 * 256 * 4)   // 131072 B

__global__ __launch_bounds__(256) void lif_scan_kernel(float* __restrict__ out)
{
    extern __shared__ float ys[];   // [w][e] : ys[w*256 + e]
    const int tid  = threadIdx.x;
    const int bid  = blockIdx.x;
    const int half = bid & 1;
    const int hb   = bid >> 1;
    const int b    = hb & 7;
    const int h    = hb >> 3;

    // base of (h, w=0, b, e-half)
    const size_t base = ((size_t)h * WD * BB + b) * DD + half * 256;
    const size_t wstride = (size_t)BB * DD;   // 4096

    // stage: 128 w x 256 e floats, float4 loads (coalesced)
#pragma unroll 8
    for (int idx = tid; idx < 128 * 64; idx += 256) {
        const int w  = idx >> 6;
        const int e4 = idx & 63;
        float4 v = *(const float4*)(g_y + base + (size_t)w * wstride + e4 * 4);
        *(float4*)&ys[w * 256 + e4 * 4] = v;
    }
    __syncthreads();

    unsigned fw[4] = {0u, 0u, 0u, 0u};
    unsigned bw[4] = {0u, 0u, 0u, 0u};
    bool flag = false;

    {
        float v = 0.0f;
#pragma unroll 8
        for (int w = 0; w < WD; ++w) {
            float yt = ys[w * 256 + tid];
            v = v + (yt - v) * 0.5f;
            flag |= (fabsf(v - 1.0f) < GUARD);
            if (v - 1.0f >= 0.0f) {
                fw[w >> 5] |= 1u << (w & 31);
                v = 0.0f;
            }
        }
    }
    {
        float v = 0.0f;
#pragma unroll 8
        for (int w = WD - 1; w >= 0; --w) {
            float yt = ys[w * 256 + tid];
            v = v + (yt - v) * 0.5f;
            flag |= (fabsf(v - 1.0f) < GUARD);
            if (v - 1.0f >= 0.0f) {
                bw[w >> 5] |= 1u << (w & 31);
                v = 0.0f;
            }
        }
    }

    float* op = out + base + tid;
#pragma unroll 8
    for (int w = 0; w < WD; ++w) {
        float s = (float)(((fw[w >> 5] >> (w & 31)) & 1u) +
                          ((bw[w >> 5] >> (w & 31)) & 1u));
        op[(size_t)w * wstride] = s;
    }

    if (flag) {
        int idx = atomicAdd(&g_ecnt[hb], 1);
        if (idx < CAP) g_elist[hb][idx] = (unsigned short)(half * 256 + tid);
    }
}

// ---------------------------------------------------------------------------
// Correction (unchanged): one block per (h,b); recompute flagged e-columns
// exactly (ascending-k fp32 scalar FMA), redo both scans, overwrite out.
// ---------------------------------------------------------------------------
#define CSM_XS 0
#define CSM_WS (64 * 128)
#define CSM_YB (CSM_WS + 8 * 512)
#define CSM_TOTAL ((CSM_YB + 8 * 128) * 4)   // 53248 B

__global__ __launch_bounds__(256) void correct_kernel(
    const float* __restrict__ x,
    const float* __restrict__ Wl,
    const float* __restrict__ bias,
    float* __restrict__ out)
{
    extern __shared__ float csm[];
    float* xs   = csm + CSM_XS;
    float* ws   = csm + CSM_WS;
    float* ybuf = csm + CSM_YB;

    const int hb = blockIdx.x;
    int cnt = g_ecnt[hb];
    if (cnt <= 0) return;
    if (cnt > CAP) cnt = CAP;

    const int h = hb >> 3, b = hb & 7;
    const int tid = threadIdx.x, wrp = tid >> 5, lane = tid & 31;
    const size_t cbase = ((size_t)(h * WD) * BB + b) * DD;

    for (int ebase = 0; ebase < cnt; ebase += 8) {
        int e = -1;
        float be = 0.0f;
        if (ebase + wrp < cnt) {
            e = g_elist[hb][ebase + wrp];
            be = bias[e];
            const float4* wr = (const float4*)(Wl + (size_t)e * 512);
            float4* wd = (float4*)(ws + wrp * 512);
            for (int j = lane; j < 128; j += 32) wd[j] = wr[j];
        }

        float a0 = 0.f, a1 = 0.f, a2 = 0.f, a3 = 0.f;
        for (int ck = 0; ck < 8; ++ck) {
            __syncthreads();
#pragma unroll
            for (int i = 0; i < 2; ++i) {
                const int w = (tid >> 2) + i * 64;
                const float4* xr = (const float4*)(x + cbase +
                                                   (size_t)w * 4096 + ck * 64);
#pragma unroll
                for (int j = 0; j < 4; ++j) {
                    const int k4 = (tid & 3) + j * 4;
                    float4 v = xr[k4];
                    xs[(k4 * 4 + 0) * 128 + w] = v.x;
                    xs[(k4 * 4 + 1) * 128 + w] = v.y;
                    xs[(k4 * 4 + 2) * 128 + w] = v.z;
                    xs[(k4 * 4 + 3) * 128 + w] = v.w;
                }
            }
            __syncthreads();
            if (e >= 0) {
                const float* wc = ws + wrp * 512 + ck * 64;
                for (int kk = 0; kk < 64; ++kk) {
                    const float wv = wc[kk];
                    a0 = fmaf(xs[kk * 128 + lane],      wv, a0);
                    a1 = fmaf(xs[kk * 128 + lane + 32], wv, a1);
                    a2 = fmaf(xs[kk * 128 + lane + 64], wv, a2);
                    a3 = fmaf(xs[kk * 128 + lane + 96], wv, a3);
                }
            }
        }

        unsigned bits[4] = {0u, 0u, 0u, 0u};
        if (e >= 0) {
            ybuf[wrp * 128 + lane]      = a0 + be;
            ybuf[wrp * 128 + lane + 32] = a1 + be;
            ybuf[wrp * 128 + lane + 64] = a2 + be;
            ybuf[wrp * 128 + lane + 96] = a3 + be;
        }
        __syncwarp();
        if (e >= 0 && lane < 2) {
            float v = 0.0f;
            for (int i = 0; i < WD; ++i) {
                const int w = lane ? (WD - 1 - i) : i;
                float yt = ybuf[wrp * 128 + w];
                v = v + (yt - v) * 0.5f;
                if (v - 1.0f >= 0.0f) { bits[w >> 5] |= 1u << (w & 31); v = 0.0f; }
            }
        }
        unsigned fwv[4], bwv[4];
#pragma unroll
        for (int i = 0; i < 4; ++i) {
            fwv[i] = __shfl_sync(0xFFFFFFFFu, bits[i], 0);
            bwv[i] = __shfl_sync(0xFFFFFFFFu, bits[i], 1);
        }
        if (e >= 0) {
#pragma unroll
            for (int c = 0; c < 4; ++c) {
                const int w = lane + 32 * c;
                float s = (float)(((fwv[w >> 5] >> (w & 31)) & 1u) +
                                  ((bwv[w >> 5] >> (w & 31)) & 1u));
                out[cbase + (size_t)w * 4096 + e] = s;
            }
        }
        __syncthreads();
    }
}

extern "C" void kernel_launch(void* const* d_in, const int* in_sizes, int n_in,
                              void* d_out, int out_size)
{
    const float* x    = (const float*)d_in[0];   // (16384, 8, 512) fp32
    const float* Wlin = (const float*)d_in[1];   // (512, 512) fp32
    const float* blin = (const float*)d_in[2];   // (512,) fp32
    float* out = (float*)d_out;

    cudaFuncSetAttribute(gemm_tc_kernel,
                         cudaFuncAttributeMaxDynamicSharedMemorySize, SMEM_GEMM);
    cudaFuncSetAttribute(lif_scan_kernel,
                         cudaFuncAttributeMaxDynamicSharedMemorySize, SCAN_SMEM);
    cudaFuncSetAttribute(correct_kernel,
                         cudaFuncAttributeMaxDynamicSharedMemorySize, CSM_TOTAL);

    const int xblocks = (int)(X_ELEMS / 1024);
    const int wblocks = (int)(W_ELEMS / 1024);
    split_kernel<<<xblocks + wblocks, 256>>>(x, Wlin);

    dim3 ggrid(4, 1024);
    gemm_tc_kernel<<<ggrid, 256, SMEM_GEMM>>>(blin);

    lif_scan_kernel<<<HH * BB * 2, 256, SCAN_SMEM>>>(out);

    correct_kernel<<<HH * BB, 256, CSM_TOTAL>>>(x, Wlin, blin, out);
}

// round 13
// speedup vs baseline: 1.1532x; 1.1532x over previous
#include <cuda_runtime.h>
#include <cuda_fp16.h>
#include <cstdint>

// Problem dims
#define HH 128
#define WD 128
#define BB 8
#define DD 512
#define M_TOTAL (HH * WD * BB)   // 131072 rows
#define X_ELEMS ((size_t)M_TOTAL * DD)
#define W_ELEMS ((size_t)DD * DD)
#define GUARD 2e-5f
#define CAP 128

// Scratch
__device__ float g_y[(size_t)M_TOTAL * DD];
__device__ __half g_x0[X_ELEMS];
__device__ __half g_x1[X_ELEMS];
__device__ __half g_w0[W_ELEMS];
__device__ __half g_w1[W_ELEMS];
__device__ int g_ecnt[HH * BB];
__device__ unsigned short g_elist[HH * BB][CAP];

// ---------------------------------------------------------------------------
// MMA / LDSM / cp.async macros
// ---------------------------------------------------------------------------
#define MMA_ZERO(d, a, b0, b1)                                               \
    asm volatile(                                                            \
        "mma.sync.aligned.m16n8k16.row.col.f32.f16.f16.f32 "                \
        "{%0,%1,%2,%3}, {%4,%5,%6,%7}, {%8,%9}, {%10,%10,%10,%10};"         \
        : "=f"((d)[0]), "=f"((d)[1]), "=f"((d)[2]), "=f"((d)[3])             \
        : "r"((a)[0]), "r"((a)[1]), "r"((a)[2]), "r"((a)[3]),                \
          "r"(b0), "r"(b1), "f"(0.0f))

#define MMA_ACC(d, a, b0, b1)                                                \
    asm volatile(                                                            \
        "mma.sync.aligned.m16n8k16.row.col.f32.f16.f16.f32 "                \
        "{%0,%1,%2,%3}, {%4,%5,%6,%7}, {%8,%9}, {%0,%1,%2,%3};"             \
        : "+f"((d)[0]), "+f"((d)[1]), "+f"((d)[2]), "+f"((d)[3])             \
        : "r"((a)[0]), "r"((a)[1]), "r"((a)[2]), "r"((a)[3]),                \
          "r"(b0), "r"(b1))

#define LDSM_X4(r, addr)                                                     \
    asm volatile(                                                            \
        "ldmatrix.sync.aligned.m8n8.x4.shared.b16 {%0,%1,%2,%3}, [%4];"     \
        : "=r"((r)[0]), "=r"((r)[1]), "=r"((r)[2]), "=r"((r)[3])             \
        : "r"(addr))

#define CP_ASYNC(dst, src)                                                   \
    asm volatile("cp.async.cg.shared.global [%0], [%1], 16;"                \
                 :: "r"(dst), "l"(src) : "memory")
#define CP_COMMIT()  asm volatile("cp.async.commit_group;" ::: "memory")
#define CP_WAIT0()   asm volatile("cp.async.wait_group 0;" ::: "memory")

// SMEM geometry (uint32 units): [row 0..127][kp 0..15] stride 20.
// 4 arrays per stage (A0, A1, W0, W1), 2 stages.
#define RST  20
#define ARR  (128 * RST)        // 2560 u32 = 10240 B
#define SSTG (4 * ARR)
#define SMEM_GEMM (2 * SSTG * 4)  // 81920 B

__device__ __forceinline__ uint32_t smem_u32(const void* p) {
    uint32_t a;
    asm("{ .reg .u64 t; cvta.to.shared.u64 t, %1; cvt.u32.u64 %0, t; }"
        : "=r"(a) : "l"(p));
    return a;
}

// ---------------------------------------------------------------------------
// Pre-split: fp32 -> fp16 hi/lo
// ---------------------------------------------------------------------------
__global__ __launch_bounds__(256) void split_kernel(
    const float* __restrict__ x, const float* __restrict__ w)
{
    const int tid = threadIdx.x;
    if (blockIdx.x == 0) {
        for (int i = tid; i < HH * BB; i += 256) g_ecnt[i] = 0;
    }
    size_t i4 = ((size_t)blockIdx.x * 256 + tid) * 4;
    const float* src;
    __half *d0, *d1;
    if (i4 < X_ELEMS) {
        src = x + i4; d0 = g_x0 + i4; d1 = g_x1 + i4;
    } else {
        i4 -= X_ELEMS;
        if (i4 >= W_ELEMS) return;
        src = w + i4; d0 = g_w0 + i4; d1 = g_w1 + i4;
    }
    float4 v = *(const float4*)src;
    const float f[4] = {v.x, v.y, v.z, v.w};
    unsigned short h[4], l[4];
#pragma unroll
    for (int j = 0; j < 4; ++j) {
        __half hh = __float2half_rn(f[j]);
        __half ll = __float2half_rn(f[j] - __half2float(hh));
        h[j] = __half_as_ushort(hh);
        l[j] = __half_as_ushort(ll);
    }
    *(uint2*)d0 = make_uint2((uint32_t)h[0] | ((uint32_t)h[1] << 16),
                             (uint32_t)h[2] | ((uint32_t)h[3] << 16));
    *(uint2*)d1 = make_uint2((uint32_t)l[0] | ((uint32_t)l[1] << 16),
                             (uint32_t)l[2] | ((uint32_t)l[3] << 16));
}

// ---------------------------------------------------------------------------
// GEMM: fp16 2-level split, 3 passes; TWO independent 3-MMA chains per
// (mt,nt) per 32-k (double chain ILP), FADD master. CTA 128x128, BK=32,
// 8 warps (2M x 4N), ldmatrix, cp.async, double-buffered, 2 CTAs/SM.
// ---------------------------------------------------------------------------
__global__ __launch_bounds__(256, 2) void gemm_tc_kernel(
    const float* __restrict__ bias)
{
    extern __shared__ uint32_t smem[];
    const uint32_t sb = smem_u32(smem);

    const int tid  = threadIdx.x;
    const int lane = tid & 31;
    const int wid  = tid >> 5;
    const int wm   = wid >> 2;        // 0..1
    const int wn   = wid & 3;         // 0..3

    const int m0 = blockIdx.y << 7;
    const int n0 = blockIdx.x << 7;

    const int prow  = tid >> 1;
    const int cpair = (tid & 1) << 1;
    const __half* src[4];
    src[0] = g_x0 + (size_t)(m0 + prow) * 512 + cpair * 8;
    src[1] = g_x1 + (size_t)(m0 + prow) * 512 + cpair * 8;
    src[2] = g_w0 + (size_t)(n0 + prow) * 512 + cpair * 8;
    src[3] = g_w1 + (size_t)(n0 + prow) * 512 + cpair * 8;
    const uint32_t dstb = sb + 4 * (prow * RST + cpair * 4);

    const uint32_t a_off = ((wm << 6) + (lane & 15)) * RST + ((lane >> 4) << 2);
    const uint32_t b_off = ((wn << 5) + ((lane >> 4) << 3) + (lane & 7)) * RST +
                           (((lane >> 3) & 1) << 2);

    float acc[4][4][4];
#pragma unroll
    for (int mt = 0; mt < 4; ++mt)
#pragma unroll
        for (int nt = 0; nt < 4; ++nt)
#pragma unroll
            for (int r = 0; r < 4; ++r) acc[mt][nt][r] = 0.0f;

#pragma unroll
    for (int arr = 0; arr < 4; ++arr) {
#pragma unroll
        for (int c = 0; c < 2; ++c)
            CP_ASYNC(dstb + 4 * (arr * ARR) + c * 16, src[arr] + c * 8);
    }
    CP_COMMIT();

    for (int it = 0; it < 16; ++it) {
        const uint32_t stg = (it & 1) ? (uint32_t)SSTG : 0u;

        CP_WAIT0();
        __syncthreads();

        if (it < 15) {
            const uint32_t nst = (it & 1) ? 0u : (uint32_t)SSTG;
            const int koff = (it + 1) * 32;
#pragma unroll
            for (int arr = 0; arr < 4; ++arr) {
#pragma unroll
                for (int c = 0; c < 2; ++c)
                    CP_ASYNC(dstb + 4 * (nst + arr * ARR) + c * 16,
                             src[arr] + koff + c * 8);
            }
            CP_COMMIT();
        }

        uint32_t bfr[2][2][2][4];   // [lvl][ks][ntp][4]
#pragma unroll
        for (int lvl = 0; lvl < 2; ++lvl)
#pragma unroll
            for (int ks = 0; ks < 2; ++ks)
#pragma unroll
                for (int ntp = 0; ntp < 2; ++ntp) {
                    const uint32_t addr = sb + 4 * (stg + (2 + lvl) * ARR +
                                                    b_off + ks * 8 + ntp * 320);
                    LDSM_X4(bfr[lvl][ks][ntp], addr);
                }

#pragma unroll
        for (int mt = 0; mt < 4; ++mt) {
            uint32_t af[2][2][4];   // [lvl][ks][4]
#pragma unroll
            for (int lvl = 0; lvl < 2; ++lvl)
#pragma unroll
                for (int ks = 0; ks < 2; ++ks) {
                    const uint32_t addr = sb + 4 * (stg + lvl * ARR + a_off +
                                                    ks * 8 + mt * 320);
                    LDSM_X4(af[lvl][ks], addr);
                }
#pragma unroll
            for (int nt = 0; nt < 4; ++nt) {
                const int ntp = nt >> 1, so = (nt & 1) << 1;
                float d0[4], d1[4];
                // two independent 3-MMA chains (small terms first in each)
                MMA_ZERO(d0, af[1][0], bfr[0][0][ntp][so], bfr[0][0][ntp][so + 1]); // a1b0 k0
                MMA_ZERO(d1, af[0][1], bfr[1][1][ntp][so], bfr[1][1][ntp][so + 1]); // a0b1 k1
                MMA_ACC(d0, af[1][1], bfr[0][1][ntp][so], bfr[0][1][ntp][so + 1]);  // a1b0 k1
                MMA_ACC(d1, af[0][0], bfr[0][0][ntp][so], bfr[0][0][ntp][so + 1]);  // a0b0 k0
                MMA_ACC(d0, af[0][0], bfr[1][0][ntp][so], bfr[1][0][ntp][so + 1]);  // a0b1 k0
                MMA_ACC(d1, af[0][1], bfr[0][1][ntp][so], bfr[0][1][ntp][so + 1]);  // a0b0 k1
#pragma unroll
                for (int r = 0; r < 4; ++r)
                    acc[mt][nt][r] += d0[r] + d1[r];
            }
        }
    }

    const int q = lane & 3;
    const int r = lane >> 2;
#pragma unroll
    for (int nt = 0; nt < 4; ++nt) {
        const int col = n0 + (wn << 5) + (nt << 3) + (q << 1);
        const float2 bb = *(const float2*)&bias[col];
#pragma unroll
        for (int mt = 0; mt < 4; ++mt) {
            const int rrow = m0 + (wm << 6) + (mt << 4) + r;
            float2 v0, v1;
            v0.x = acc[mt][nt][0] + bb.x;
            v0.y = acc[mt][nt][1] + bb.y;
            v1.x = acc[mt][nt][2] + bb.x;
            v1.y = acc[mt][nt][3] + bb.y;
            *(float2*)&g_y[(size_t)rrow * 512 + col]       = v0;
            *(float2*)&g_y[(size_t)(rrow + 8) * 512 + col] = v1;
        }
    }
}

// ---------------------------------------------------------------------------
// Bidirectional LIF scan + flagging (R11 v1: direct reads, high occupancy)
// ---------------------------------------------------------------------------
__global__ __launch_bounds__(256) void lif_scan_kernel(float* __restrict__ out)
{
    const int g = blockIdx.x * 256 + threadIdx.x;
    const int e = g & (DD - 1);
    const int b = (g >> 9) & (BB - 1);
    const int h = g >> 12;

    const size_t base = ((size_t)h * WD * BB + b) * DD + e;
    const float* yp = g_y + base;
    const size_t wstride = (size_t)BB * DD;

    unsigned fw[4] = {0u, 0u, 0u, 0u};
    unsigned bw[4] = {0u, 0u, 0u, 0u};
    bool flag = false;

    {
        float v = 0.0f;
#pragma unroll 8
        for (int w = 0; w < WD; ++w) {
            float yt = yp[(size_t)w * wstride];
            v = v + (yt - v) * 0.5f;
            flag |= (fabsf(v - 1.0f) < GUARD);
            if (v - 1.0f >= 0.0f) {
                fw[w >> 5] |= 1u << (w & 31);
                v = 0.0f;
            }
        }
    }
    {
        float v = 0.0f;
#pragma unroll 8
        for (int w = WD - 1; w >= 0; --w) {
            float yt = yp[(size_t)w * wstride];
            v = v + (yt - v) * 0.5f;
            flag |= (fabsf(v - 1.0f) < GUARD);
            if (v - 1.0f >= 0.0f) {
                bw[w >> 5] |= 1u << (w & 31);
                v = 0.0f;
            }
        }
    }

    float* op = out + base;
#pragma unroll
    for (int w = 0; w < WD; ++w) {
        float s = (float)(((fw[w >> 5] >> (w & 31)) & 1u) +
                          ((bw[w >> 5] >> (w & 31)) & 1u));
        op[(size_t)w * wstride] = s;
    }

    if (flag) {
        const int hb = g >> 9;
        int idx = atomicAdd(&g_ecnt[hb], 1);
        if (idx < CAP) g_elist[hb][idx] = (unsigned short)e;
    }
}

// ---------------------------------------------------------------------------
// Correction: one block per (h,b); recompute flagged e-columns exactly
// (ascending-k fp32 scalar FMA), redo both scans, overwrite out.
// ---------------------------------------------------------------------------
#define CSM_XS 0
#define CSM_WS (64 * 128)
#define CSM_YB (CSM_WS + 8 * 512)
#define CSM_TOTAL ((CSM_YB + 8 * 128) * 4)   // 53248 B

__global__ __launch_bounds__(256) void correct_kernel(
    const float* __restrict__ x,
    const float* __restrict__ Wl,
    const float* __restrict__ bias,
    float* __restrict__ out)
{
    extern __shared__ float csm[];
    float* xs   = csm + CSM_XS;
    float* ws   = csm + CSM_WS;
    float* ybuf = csm + CSM_YB;

    const int hb = blockIdx.x;
    int cnt = g_ecnt[hb];
    if (cnt <= 0) return;
    if (cnt > CAP) cnt = CAP;

    const int h = hb >> 3, b = hb & 7;
    const int tid = threadIdx.x, wrp = tid >> 5, lane = tid & 31;
    const size_t cbase = ((size_t)(h * WD) * BB + b) * DD;

    for (int ebase = 0; ebase < cnt; ebase += 8) {
        int e = -1;
        float be = 0.0f;
        if (ebase + wrp < cnt) {
            e = g_elist[hb][ebase + wrp];
            be = bias[e];
            const float4* wr = (const float4*)(Wl + (size_t)e * 512);
            float4* wd = (float4*)(ws + wrp * 512);
            for (int j = lane; j < 128; j += 32) wd[j] = wr[j];
        }

        float a0 = 0.f, a1 = 0.f, a2 = 0.f, a3 = 0.f;
        for (int ck = 0; ck < 8; ++ck) {
            __syncthreads();
#pragma unroll
            for (int i = 0; i < 2; ++i) {
                const int w = (tid >> 2) + i * 64;
                const float4* xr = (const float4*)(x + cbase +
                                                   (size_t)w * 4096 + ck * 64);
#pragma unroll
                for (int j = 0; j < 4; ++j) {
                    const int k4 = (tid & 3) + j * 4;
                    float4 v = xr[k4];
                    xs[(k4 * 4 + 0) * 128 + w] = v.x;
                    xs[(k4 * 4 + 1) * 128 + w] = v.y;
                    xs[(k4 * 4 + 2) * 128 + w] = v.z;
                    xs[(k4 * 4 + 3) * 128 + w] = v.w;
                }
            }
            __syncthreads();
            if (e >= 0) {
                const float* wc = ws + wrp * 512 + ck * 64;
                for (int kk = 0; kk < 64; ++kk) {
                    const float wv = wc[kk];
                    a0 = fmaf(xs[kk * 128 + lane],      wv, a0);
                    a1 = fmaf(xs[kk * 128 + lane + 32], wv, a1);
                    a2 = fmaf(xs[kk * 128 + lane + 64], wv, a2);
                    a3 = fmaf(xs[kk * 128 + lane + 96], wv, a3);
                }
            }
        }

        unsigned bits[4] = {0u, 0u, 0u, 0u};
        if (e >= 0) {
            ybuf[wrp * 128 + lane]      = a0 + be;
            ybuf[wrp * 128 + lane + 32] = a1 + be;
            ybuf[wrp * 128 + lane + 64] = a2 + be;
            ybuf[wrp * 128 + lane + 96] = a3 + be;
        }
        __syncwarp();
        if (e >= 0 && lane < 2) {
            float v = 0.0f;
            for (int i = 0; i < WD; ++i) {
                const int w = lane ? (WD - 1 - i) : i;
                float yt = ybuf[wrp * 128 + w];
                v = v + (yt - v) * 0.5f;
                if (v - 1.0f >= 0.0f) { bits[w >> 5] |= 1u << (w & 31); v = 0.0f; }
            }
        }
        unsigned fwv[4], bwv[4];
#pragma unroll
        for (int i = 0; i < 4; ++i) {
            fwv[i] = __shfl_sync(0xFFFFFFFFu, bits[i], 0);
            bwv[i] = __shfl_sync(0xFFFFFFFFu, bits[i], 1);
        }
        if (e >= 0) {
#pragma unroll
            for (int c = 0; c < 4; ++c) {
                const int w = lane + 32 * c;
                float s = (float)(((fwv[w >> 5] >> (w & 31)) & 1u) +
                                  ((bwv[w >> 5] >> (w & 31)) & 1u));
                out[cbase + (size_t)w * 4096 + e] = s;
            }
        }
        __syncthreads();
    }
}

extern "C" void kernel_launch(void* const* d_in, const int* in_sizes, int n_in,
                              void* d_out, int out_size)
{
    const float* x    = (const float*)d_in[0];   // (16384, 8, 512) fp32
    const float* Wlin = (const float*)d_in[1];   // (512, 512) fp32
    const float* blin = (const float*)d_in[2];   // (512,) fp32
    float* out = (float*)d_out;

    cudaFuncSetAttribute(gemm_tc_kernel,
                         cudaFuncAttributeMaxDynamicSharedMemorySize, SMEM_GEMM);
    cudaFuncSetAttribute(correct_kernel,
                         cudaFuncAttributeMaxDynamicSharedMemorySize, CSM_TOTAL);

    const int xblocks = (int)(X_ELEMS / 1024);
    const int wblocks = (int)(W_ELEMS / 1024);
    split_kernel<<<xblocks + wblocks, 256>>>(x, Wlin);

    dim3 ggrid(4, 1024);
    gemm_tc_kernel<<<ggrid, 256, SMEM_GEMM>>>(blin);

    lif_scan_kernel<<<(HH * BB * DD) / 256, 256>>>(out);

    correct_kernel<<<HH * BB, 256, CSM_TOTAL>>>(x, Wlin, blin, out);
}

// round 14
// speedup vs baseline: 1.2566x; 1.0897x over previous
#include <cuda_runtime.h>
#include <cuda_fp16.h>
#include <cstdint>

// Problem dims
#define HH 128
#define WD 128
#define BB 8
#define DD 512
#define M_TOTAL (HH * WD * BB)   // 131072 rows
#define X_ELEMS ((size_t)M_TOTAL * DD)
#define W_ELEMS ((size_t)DD * DD)
#define GUARD 2e-5f
#define CAP 128

// Scratch
__device__ float g_y[(size_t)M_TOTAL * DD];
__device__ __half g_x0[X_ELEMS];
__device__ __half g_x1[X_ELEMS];
__device__ __half g_w0[W_ELEMS];
__device__ __half g_w1[W_ELEMS];
__device__ int g_ecnt[HH * BB];
__device__ unsigned short g_elist[HH * BB][CAP];

// ---------------------------------------------------------------------------
// MMA / LDSM / cp.async macros
// ---------------------------------------------------------------------------
#define MMA_ZERO(d, a, b0, b1)                                               \
    asm volatile(                                                            \
        "mma.sync.aligned.m16n8k16.row.col.f32.f16.f16.f32 "                \
        "{%0,%1,%2,%3}, {%4,%5,%6,%7}, {%8,%9}, {%10,%10,%10,%10};"         \
        : "=f"((d)[0]), "=f"((d)[1]), "=f"((d)[2]), "=f"((d)[3])             \
        : "r"((a)[0]), "r"((a)[1]), "r"((a)[2]), "r"((a)[3]),                \
          "r"(b0), "r"(b1), "f"(0.0f))

#define MMA_ACC(d, a, b0, b1)                                                \
    asm volatile(                                                            \
        "mma.sync.aligned.m16n8k16.row.col.f32.f16.f16.f32 "                \
        "{%0,%1,%2,%3}, {%4,%5,%6,%7}, {%8,%9}, {%0,%1,%2,%3};"             \
        : "+f"((d)[0]), "+f"((d)[1]), "+f"((d)[2]), "+f"((d)[3])             \
        : "r"((a)[0]), "r"((a)[1]), "r"((a)[2]), "r"((a)[3]),                \
          "r"(b0), "r"(b1))

#define LDSM_X4(r, addr)                                                     \
    asm volatile(                                                            \
        "ldmatrix.sync.aligned.m8n8.x4.shared.b16 {%0,%1,%2,%3}, [%4];"     \
        : "=r"((r)[0]), "=r"((r)[1]), "=r"((r)[2]), "=r"((r)[3])             \
        : "r"(addr))

#define CP_ASYNC(dst, src)                                                   \
    asm volatile("cp.async.cg.shared.global [%0], [%1], 16;"                \
                 :: "r"(dst), "l"(src) : "memory")
#define CP_COMMIT()  asm volatile("cp.async.commit_group;" ::: "memory")
#define CP_WAIT0()   asm volatile("cp.async.wait_group 0;" ::: "memory")

// SMEM geometry (uint32 units): [row 0..127][kp 0..15] stride 20.
// 4 arrays per stage (A0, A1, W0, W1), 2 stages.
#define RST  20
#define ARR  (128 * RST)        // 2560 u32 = 10240 B
#define SSTG (4 * ARR)
#define SMEM_GEMM (2 * SSTG * 4)  // 81920 B

__device__ __forceinline__ uint32_t smem_u32(const void* p) {
    uint32_t a;
    asm("{ .reg .u64 t; cvta.to.shared.u64 t, %1; cvt.u32.u64 %0, t; }"
        : "=r"(a) : "l"(p));
    return a;
}

// ---------------------------------------------------------------------------
// Pre-split: fp32 -> fp16 hi/lo
// ---------------------------------------------------------------------------
__global__ __launch_bounds__(256) void split_kernel(
    const float* __restrict__ x, const float* __restrict__ w)
{
    const int tid = threadIdx.x;
    if (blockIdx.x == 0) {
        for (int i = tid; i < HH * BB; i += 256) g_ecnt[i] = 0;
    }
    size_t i4 = ((size_t)blockIdx.x * 256 + tid) * 4;
    const float* src;
    __half *d0, *d1;
    if (i4 < X_ELEMS) {
        src = x + i4; d0 = g_x0 + i4; d1 = g_x1 + i4;
    } else {
        i4 -= X_ELEMS;
        if (i4 >= W_ELEMS) return;
        src = w + i4; d0 = g_w0 + i4; d1 = g_w1 + i4;
    }
    float4 v = *(const float4*)src;
    const float f[4] = {v.x, v.y, v.z, v.w};
    unsigned short h[4], l[4];
#pragma unroll
    for (int j = 0; j < 4; ++j) {
        __half hh = __float2half_rn(f[j]);
        __half ll = __float2half_rn(f[j] - __half2float(hh));
        h[j] = __half_as_ushort(hh);
        l[j] = __half_as_ushort(ll);
    }
    *(uint2*)d0 = make_uint2((uint32_t)h[0] | ((uint32_t)h[1] << 16),
                             (uint32_t)h[2] | ((uint32_t)h[3] << 16));
    *(uint2*)d1 = make_uint2((uint32_t)l[0] | ((uint32_t)l[1] << 16),
                             (uint32_t)l[2] | ((uint32_t)l[3] << 16));
}

// ---------------------------------------------------------------------------
// GEMM (FROZEN R11 config): fp16 2-level split, 3 passes; 6-MMA fresh chain,
// FADD master. CTA 128x128, BK=32, 8 warps (2M x 4N), ldmatrix, cp.async,
// double-buffered, 2 CTAs/SM.
// ---------------------------------------------------------------------------
__global__ __launch_bounds__(256, 2) void gemm_tc_kernel(
    const float* __restrict__ bias)
{
    extern __shared__ uint32_t smem[];
    const uint32_t sb = smem_u32(smem);

    const int tid  = threadIdx.x;
    const int lane = tid & 31;
    const int wid  = tid >> 5;
    const int wm   = wid >> 2;        // 0..1
    const int wn   = wid & 3;         // 0..3

    const int m0 = blockIdx.y << 7;
    const int n0 = blockIdx.x << 7;

    const int prow  = tid >> 1;
    const int cpair = (tid & 1) << 1;
    const __half* src[4];
    src[0] = g_x0 + (size_t)(m0 + prow) * 512 + cpair * 8;
    src[1] = g_x1 + (size_t)(m0 + prow) * 512 + cpair * 8;
    src[2] = g_w0 + (size_t)(n0 + prow) * 512 + cpair * 8;
    src[3] = g_w1 + (size_t)(n0 + prow) * 512 + cpair * 8;
    const uint32_t dstb = sb + 4 * (prow * RST + cpair * 4);

    const uint32_t a_off = ((wm << 6) + (lane & 15)) * RST + ((lane >> 4) << 2);
    const uint32_t b_off = ((wn << 5) + ((lane >> 4) << 3) + (lane & 7)) * RST +
                           (((lane >> 3) & 1) << 2);

    float acc[4][4][4];
#pragma unroll
    for (int mt = 0; mt < 4; ++mt)
#pragma unroll
        for (int nt = 0; nt < 4; ++nt)
#pragma unroll
            for (int r = 0; r < 4; ++r) acc[mt][nt][r] = 0.0f;

#pragma unroll
    for (int arr = 0; arr < 4; ++arr) {
#pragma unroll
        for (int c = 0; c < 2; ++c)
            CP_ASYNC(dstb + 4 * (arr * ARR) + c * 16, src[arr] + c * 8);
    }
    CP_COMMIT();

    for (int it = 0; it < 16; ++it) {
        const uint32_t stg = (it & 1) ? (uint32_t)SSTG : 0u;

        CP_WAIT0();
        __syncthreads();

        if (it < 15) {
            const uint32_t nst = (it & 1) ? 0u : (uint32_t)SSTG;
            const int koff = (it + 1) * 32;
#pragma unroll
            for (int arr = 0; arr < 4; ++arr) {
#pragma unroll
                for (int c = 0; c < 2; ++c)
                    CP_ASYNC(dstb + 4 * (nst + arr * ARR) + c * 16,
                             src[arr] + koff + c * 8);
            }
            CP_COMMIT();
        }

        uint32_t bfr[2][2][2][4];
#pragma unroll
        for (int lvl = 0; lvl < 2; ++lvl)
#pragma unroll
            for (int ks = 0; ks < 2; ++ks)
#pragma unroll
                for (int ntp = 0; ntp < 2; ++ntp) {
                    const uint32_t addr = sb + 4 * (stg + (2 + lvl) * ARR +
                                                    b_off + ks * 8 + ntp * 320);
                    LDSM_X4(bfr[lvl][ks][ntp], addr);
                }

#pragma unroll
        for (int mt = 0; mt < 4; ++mt) {
            uint32_t af[2][2][4];
#pragma unroll
            for (int lvl = 0; lvl < 2; ++lvl)
#pragma unroll
                for (int ks = 0; ks < 2; ++ks) {
                    const uint32_t addr = sb + 4 * (stg + lvl * ARR + a_off +
                                                    ks * 8 + mt * 320);
                    LDSM_X4(af[lvl][ks], addr);
                }
#pragma unroll
            for (int nt = 0; nt < 4; ++nt) {
                const int ntp = nt >> 1, so = (nt & 1) << 1;
                float d[4];
                MMA_ZERO(d, af[1][0], bfr[0][0][ntp][so], bfr[0][0][ntp][so + 1]);
                MMA_ACC(d, af[1][1], bfr[0][1][ntp][so], bfr[0][1][ntp][so + 1]);
                MMA_ACC(d, af[0][0], bfr[1][0][ntp][so], bfr[1][0][ntp][so + 1]);
                MMA_ACC(d, af[0][1], bfr[1][1][ntp][so], bfr[1][1][ntp][so + 1]);
                MMA_ACC(d, af[0][0], bfr[0][0][ntp][so], bfr[0][0][ntp][so + 1]);
                MMA_ACC(d, af[0][1], bfr[0][1][ntp][so], bfr[0][1][ntp][so + 1]);
                acc[mt][nt][0] += d[0];
                acc[mt][nt][1] += d[1];
                acc[mt][nt][2] += d[2];
                acc[mt][nt][3] += d[3];
            }
        }
    }

    const int q = lane & 3;
    const int r = lane >> 2;
#pragma unroll
    for (int nt = 0; nt < 4; ++nt) {
        const int col = n0 + (wn << 5) + (nt << 3) + (q << 1);
        const float2 bb = *(const float2*)&bias[col];
#pragma unroll
        for (int mt = 0; mt < 4; ++mt) {
            const int rrow = m0 + (wm << 6) + (mt << 4) + r;
            float2 v0, v1;
            v0.x = acc[mt][nt][0] + bb.x;
            v0.y = acc[mt][nt][1] + bb.y;
            v1.x = acc[mt][nt][2] + bb.x;
            v1.y = acc[mt][nt][3] + bb.y;
            *(float2*)&g_y[(size_t)rrow * 512 + col]       = v0;
            *(float2*)&g_y[(size_t)(rrow + 8) * 512 + col] = v1;
        }
    }
}

// ---------------------------------------------------------------------------
// Scan v3: register-resident column. Each thread loads its 128-w column ONCE
// (independent loads, huge MLP), runs fwd+bwd scans out of registers.
// Numerics identical to v1.
// ---------------------------------------------------------------------------
__global__ __launch_bounds__(256) void lif_scan_kernel(float* __restrict__ out)
{
    const int g = blockIdx.x * 256 + threadIdx.x;
    const int e = g & (DD - 1);
    const int b = (g >> 9) & (BB - 1);
    const int h = g >> 12;

    const size_t base = ((size_t)h * WD * BB + b) * DD + e;
    const float* yp = g_y + base;
    const size_t wstride = (size_t)BB * DD;

    float y[WD];
#pragma unroll
    for (int w = 0; w < WD; ++w)
        y[w] = yp[(size_t)w * wstride];

    unsigned fw[4] = {0u, 0u, 0u, 0u};
    unsigned bw[4] = {0u, 0u, 0u, 0u};
    bool flag = false;

    {
        float v = 0.0f;
#pragma unroll
        for (int w = 0; w < WD; ++w) {
            v = v + (y[w] - v) * 0.5f;
            flag |= (fabsf(v - 1.0f) < GUARD);
            if (v - 1.0f >= 0.0f) {
                fw[w >> 5] |= 1u << (w & 31);
                v = 0.0f;
            }
        }
    }
    {
        float v = 0.0f;
#pragma unroll
        for (int w = WD - 1; w >= 0; --w) {
            v = v + (y[w] - v) * 0.5f;
            flag |= (fabsf(v - 1.0f) < GUARD);
            if (v - 1.0f >= 0.0f) {
                bw[w >> 5] |= 1u << (w & 31);
                v = 0.0f;
            }
        }
    }

    float* op = out + base;
#pragma unroll
    for (int w = 0; w < WD; ++w) {
        float s = (float)(((fw[w >> 5] >> (w & 31)) & 1u) +
                          ((bw[w >> 5] >> (w & 31)) & 1u));
        op[(size_t)w * wstride] = s;
    }

    if (flag) {
        const int hb = g >> 9;
        int idx = atomicAdd(&g_ecnt[hb], 1);
        if (idx < CAP) g_elist[hb][idx] = (unsigned short)e;
    }
}

// ---------------------------------------------------------------------------
// Correction: one block per (h,b); recompute flagged e-columns exactly
// (ascending-k fp32 scalar FMA), redo both scans, overwrite out.
// ---------------------------------------------------------------------------
#define CSM_XS 0
#define CSM_WS (64 * 128)
#define CSM_YB (CSM_WS + 8 * 512)
#define CSM_TOTAL ((CSM_YB + 8 * 128) * 4)   // 53248 B

__global__ __launch_bounds__(256) void correct_kernel(
    const float* __restrict__ x,
    const float* __restrict__ Wl,
    const float* __restrict__ bias,
    float* __restrict__ out)
{
    extern __shared__ float csm[];
    float* xs   = csm + CSM_XS;
    float* ws   = csm + CSM_WS;
    float* ybuf = csm + CSM_YB;

    const int hb = blockIdx.x;
    int cnt = g_ecnt[hb];
    if (cnt <= 0) return;
    if (cnt > CAP) cnt = CAP;

    const int h = hb >> 3, b = hb & 7;
    const int tid = threadIdx.x, wrp = tid >> 5, lane = tid & 31;
    const size_t cbase = ((size_t)(h * WD) * BB + b) * DD;

    for (int ebase = 0; ebase < cnt; ebase += 8) {
        int e = -1;
        float be = 0.0f;
        if (ebase + wrp < cnt) {
            e = g_elist[hb][ebase + wrp];
            be = bias[e];
            const float4* wr = (const float4*)(Wl + (size_t)e * 512);
            float4* wd = (float4*)(ws + wrp * 512);
            for (int j = lane; j < 128; j += 32) wd[j] = wr[j];
        }

        float a0 = 0.f, a1 = 0.f, a2 = 0.f, a3 = 0.f;
        for (int ck = 0; ck < 8; ++ck) {
            __syncthreads();
#pragma unroll
            for (int i = 0; i < 2; ++i) {
                const int w = (tid >> 2) + i * 64;
                const float4* xr = (const float4*)(x + cbase +
                                                   (size_t)w * 4096 + ck * 64);
#pragma unroll
                for (int j = 0; j < 4; ++j) {
                    const int k4 = (tid & 3) + j * 4;
                    float4 v = xr[k4];
                    xs[(k4 * 4 + 0) * 128 + w] = v.x;
                    xs[(k4 * 4 + 1) * 128 + w] = v.y;
                    xs[(k4 * 4 + 2) * 128 + w] = v.z;
                    xs[(k4 * 4 + 3) * 128 + w] = v.w;
                }
            }
            __syncthreads();
            if (e >= 0) {
                const float* wc = ws + wrp * 512 + ck * 64;
                for (int kk = 0; kk < 64; ++kk) {
                    const float wv = wc[kk];
                    a0 = fmaf(xs[kk * 128 + lane],      wv, a0);
                    a1 = fmaf(xs[kk * 128 + lane + 32], wv, a1);
                    a2 = fmaf(xs[kk * 128 + lane + 64], wv, a2);
                    a3 = fmaf(xs[kk * 128 + lane + 96], wv, a3);
                }
            }
        }

        unsigned bits[4] = {0u, 0u, 0u, 0u};
        if (e >= 0) {
            ybuf[wrp * 128 + lane]      = a0 + be;
            ybuf[wrp * 128 + lane + 32] = a1 + be;
            ybuf[wrp * 128 + lane + 64] = a2 + be;
            ybuf[wrp * 128 + lane + 96] = a3 + be;
        }
        __syncwarp();
        if (e >= 0 && lane < 2) {
            float v = 0.0f;
            for (int i = 0; i < WD; ++i) {
                const int w = lane ? (WD - 1 - i) : i;
                float yt = ybuf[wrp * 128 + w];
                v = v + (yt - v) * 0.5f;
                if (v - 1.0f >= 0.0f) { bits[w >> 5] |= 1u << (w & 31); v = 0.0f; }
            }
        }
        unsigned fwv[4], bwv[4];
#pragma unroll
        for (int i = 0; i < 4; ++i) {
            fwv[i] = __shfl_sync(0xFFFFFFFFu, bits[i], 0);
            bwv[i] = __shfl_sync(0xFFFFFFFFu, bits[i], 1);
        }
        if (e >= 0) {
#pragma unroll
            for (int c = 0; c < 4; ++c) {
                const int w = lane + 32 * c;
                float s = (float)(((fwv[w >> 5] >> (w & 31)) & 1u) +
                                  ((bwv[w >> 5] >> (w & 31)) & 1u));
                out[cbase + (size_t)w * 4096 + e] = s;
            }
        }
        __syncthreads();
    }
}

extern "C" void kernel_launch(void* const* d_in, const int* in_sizes, int n_in,
                              void* d_out, int out_size)
{
    const float* x    = (const float*)d_in[0];   // (16384, 8, 512) fp32
    const float* Wlin = (const float*)d_in[1];   // (512, 512) fp32
    const float* blin = (const float*)d_in[2];   // (512,) fp32
    float* out = (float*)d_out;

    cudaFuncSetAttribute(gemm_tc_kernel,
                         cudaFuncAttributeMaxDynamicSharedMemorySize, SMEM_GEMM);
    cudaFuncSetAttribute(correct_kernel,
                         cudaFuncAttributeMaxDynamicSharedMemorySize, CSM_TOTAL);

    const int xblocks = (int)(X_ELEMS / 1024);
    const int wblocks = (int)(W_ELEMS / 1024);
    split_kernel<<<xblocks + wblocks, 256>>>(x, Wlin);

    dim3 ggrid(4, 1024);
    gemm_tc_kernel<<<ggrid, 256, SMEM_GEMM>>>(blin);

    lif_scan_kernel<<<(HH * BB * DD) / 256, 256>>>(out);

    correct_kernel<<<HH * BB, 256, CSM_TOTAL>>>(x, Wlin, blin, out);
}

// round 15
// speedup vs baseline: 1.3677x; 1.0884x over previous
#include <cuda_runtime.h>
#include <cuda_fp16.h>
#include <cstdint>

// Problem dims
#define HH 128
#define WD 128
#define BB 8
#define DD 512
#define M_TOTAL (HH * WD * BB)   // 131072 rows
#define X_ELEMS ((size_t)M_TOTAL * DD)
#define W_ELEMS ((size_t)DD * DD)
#define GUARD 2e-5f
#define CAP 128

// Scratch
__device__ __half g_x0[X_ELEMS];
__device__ __half g_x1[X_ELEMS];
__device__ __half g_w0[W_ELEMS];
__device__ __half g_w1[W_ELEMS];
__device__ int g_ecnt[HH * BB];
__device__ unsigned short g_elist[HH * BB][CAP];

// ---------------------------------------------------------------------------
// MMA / LDSM / cp.async macros
// ---------------------------------------------------------------------------
#define MMA_ZERO(d, a, b0, b1)                                               \
    asm volatile(                                                            \
        "mma.sync.aligned.m16n8k16.row.col.f32.f16.f16.f32 "                \
        "{%0,%1,%2,%3}, {%4,%5,%6,%7}, {%8,%9}, {%10,%10,%10,%10};"         \
        : "=f"((d)[0]), "=f"((d)[1]), "=f"((d)[2]), "=f"((d)[3])             \
        : "r"((a)[0]), "r"((a)[1]), "r"((a)[2]), "r"((a)[3]),                \
          "r"(b0), "r"(b1), "f"(0.0f))

#define MMA_ACC(d, a, b0, b1)                                                \
    asm volatile(                                                            \
        "mma.sync.aligned.m16n8k16.row.col.f32.f16.f16.f32 "                \
        "{%0,%1,%2,%3}, {%4,%5,%6,%7}, {%8,%9}, {%0,%1,%2,%3};"             \
        : "+f"((d)[0]), "+f"((d)[1]), "+f"((d)[2]), "+f"((d)[3])             \
        : "r"((a)[0]), "r"((a)[1]), "r"((a)[2]), "r"((a)[3]),                \
          "r"(b0), "r"(b1))

#define LDSM_X4(r, addr)                                                     \
    asm volatile(                                                            \
        "ldmatrix.sync.aligned.m8n8.x4.shared.b16 {%0,%1,%2,%3}, [%4];"     \
        : "=r"((r)[0]), "=r"((r)[1]), "=r"((r)[2]), "=r"((r)[3])             \
        : "r"(addr))

#define CP_ASYNC(dst, src)                                                   \
    asm volatile("cp.async.cg.shared.global [%0], [%1], 16;"                \
                 :: "r"(dst), "l"(src) : "memory")
#define CP_COMMIT()  asm volatile("cp.async.commit_group;" ::: "memory")
#define CP_WAIT0()   asm volatile("cp.async.wait_group 0;" ::: "memory")

// SMEM geometry (uint32 units): [row 0..127][kp 0..15] stride 20.
// 4 arrays per stage (A0, A1, W0, W1), 2 stages. Epilogue reuses the whole
// region as float ys[128][132] (67584 B <= 81920 B).
#define RST  20
#define ARR  (128 * RST)        // 2560 u32 = 10240 B
#define SSTG (4 * ARR)
#define SMEM_GEMM (2 * SSTG * 4)  // 81920 B
#define YST  132                  // ys row stride (floats)

__device__ __forceinline__ uint32_t smem_u32(const void* p) {
    uint32_t a;
    asm("{ .reg .u64 t; cvta.to.shared.u64 t, %1; cvt.u32.u64 %0, t; }"
        : "=r"(a) : "l"(p));
    return a;
}

// ---------------------------------------------------------------------------
// Pre-split: fp32 -> fp16 hi/lo
// ---------------------------------------------------------------------------
__global__ __launch_bounds__(256) void split_kernel(
    const float* __restrict__ x, const float* __restrict__ w)
{
    const int tid = threadIdx.x;
    if (blockIdx.x == 0) {
        for (int i = tid; i < HH * BB; i += 256) g_ecnt[i] = 0;
    }
    size_t i4 = ((size_t)blockIdx.x * 256 + tid) * 4;
    const float* src;
    __half *d0, *d1;
    if (i4 < X_ELEMS) {
        src = x + i4; d0 = g_x0 + i4; d1 = g_x1 + i4;
    } else {
        i4 -= X_ELEMS;
        if (i4 >= W_ELEMS) return;
        src = w + i4; d0 = g_w0 + i4; d1 = g_w1 + i4;
    }
    float4 v = *(const float4*)src;
    const float f[4] = {v.x, v.y, v.z, v.w};
    unsigned short h[4], l[4];
#pragma unroll
    for (int j = 0; j < 4; ++j) {
        __half hh = __float2half_rn(f[j]);
        __half ll = __float2half_rn(f[j] - __half2float(hh));
        h[j] = __half_as_ushort(hh);
        l[j] = __half_as_ushort(ll);
    }
    *(uint2*)d0 = make_uint2((uint32_t)h[0] | ((uint32_t)h[1] << 16),
                             (uint32_t)h[2] | ((uint32_t)h[3] << 16));
    *(uint2*)d1 = make_uint2((uint32_t)l[0] | ((uint32_t)l[1] << 16),
                             (uint32_t)l[2] | ((uint32_t)l[3] << 16));
}

// ---------------------------------------------------------------------------
// Fused GEMM + scan: CTA tile = 128 w-rows of one (h,b) x 128 e-cols.
// GEMM core frozen from R11 (fp16 2-level split, 3 passes, 6-MMA chain,
// cp.async double-buffered, 2 CTAs/SM). Epilogue: Y -> smem -> in-CTA
// bidirectional LIF scan -> out, + marginal-column flagging.
// blockIdx.y = hb = h*8 + b; blockIdx.x = n-tile.
// ---------------------------------------------------------------------------
__global__ __launch_bounds__(256, 2) void gemm_scan_kernel(
    const float* __restrict__ bias,
    float* __restrict__ out)
{
    extern __shared__ uint32_t smem[];
    const uint32_t sb = smem_u32(smem);

    const int tid  = threadIdx.x;
    const int lane = tid & 31;
    const int wid  = tid >> 5;
    const int wm   = wid >> 2;        // 0..1
    const int wn   = wid & 3;         // 0..3

    const int hb = blockIdx.y;        // h*8 + b
    const int h  = hb >> 3;
    const int b  = hb & 7;
    const int n0 = blockIdx.x << 7;

    // producer: w-row = tid>>1; global X row = (h*128 + w)*8 + b
    const int prow  = tid >> 1;
    const int cpair = (tid & 1) << 1;
    const size_t xrow = ((size_t)(h * WD + prow) * BB + b) * 512 + cpair * 8;
    const __half* src[4];
    src[0] = g_x0 + xrow;
    src[1] = g_x1 + xrow;
    src[2] = g_w0 + (size_t)(n0 + prow) * 512 + cpair * 8;
    src[3] = g_w1 + (size_t)(n0 + prow) * 512 + cpair * 8;
    const uint32_t dstb = sb + 4 * (prow * RST + cpair * 4);

    const uint32_t a_off = ((wm << 6) + (lane & 15)) * RST + ((lane >> 4) << 2);
    const uint32_t b_off = ((wn << 5) + ((lane >> 4) << 3) + (lane & 7)) * RST +
                           (((lane >> 3) & 1) << 2);

    float acc[4][4][4];
#pragma unroll
    for (int mt = 0; mt < 4; ++mt)
#pragma unroll
        for (int nt = 0; nt < 4; ++nt)
#pragma unroll
            for (int r = 0; r < 4; ++r) acc[mt][nt][r] = 0.0f;

#pragma unroll
    for (int arr = 0; arr < 4; ++arr) {
#pragma unroll
        for (int c = 0; c < 2; ++c)
            CP_ASYNC(dstb + 4 * (arr * ARR) + c * 16, src[arr] + c * 8);
    }
    CP_COMMIT();

    for (int it = 0; it < 16; ++it) {
        const uint32_t stg = (it & 1) ? (uint32_t)SSTG : 0u;

        CP_WAIT0();
        __syncthreads();

        if (it < 15) {
            const uint32_t nst = (it & 1) ? 0u : (uint32_t)SSTG;
            const int koff = (it + 1) * 32;
#pragma unroll
            for (int arr = 0; arr < 4; ++arr) {
#pragma unroll
                for (int c = 0; c < 2; ++c)
                    CP_ASYNC(dstb + 4 * (nst + arr * ARR) + c * 16,
                             src[arr] + koff + c * 8);
            }
            CP_COMMIT();
        }

        uint32_t bfr[2][2][2][4];
#pragma unroll
        for (int lvl = 0; lvl < 2; ++lvl)
#pragma unroll
            for (int ks = 0; ks < 2; ++ks)
#pragma unroll
                for (int ntp = 0; ntp < 2; ++ntp) {
                    const uint32_t addr = sb + 4 * (stg + (2 + lvl) * ARR +
                                                    b_off + ks * 8 + ntp * 320);
                    LDSM_X4(bfr[lvl][ks][ntp], addr);
                }

#pragma unroll
        for (int mt = 0; mt < 4; ++mt) {
            uint32_t af[2][2][4];
#pragma unroll
            for (int lvl = 0; lvl < 2; ++lvl)
#pragma unroll
                for (int ks = 0; ks < 2; ++ks) {
                    const uint32_t addr = sb + 4 * (stg + lvl * ARR + a_off +
                                                    ks * 8 + mt * 320);
                    LDSM_X4(af[lvl][ks], addr);
                }
#pragma unroll
            for (int nt = 0; nt < 4; ++nt) {
                const int ntp = nt >> 1, so = (nt & 1) << 1;
                float d[4];
                MMA_ZERO(d, af[1][0], bfr[0][0][ntp][so], bfr[0][0][ntp][so + 1]);
                MMA_ACC(d, af[1][1], bfr[0][1][ntp][so], bfr[0][1][ntp][so + 1]);
                MMA_ACC(d, af[0][0], bfr[1][0][ntp][so], bfr[1][0][ntp][so + 1]);
                MMA_ACC(d, af[0][1], bfr[1][1][ntp][so], bfr[1][1][ntp][so + 1]);
                MMA_ACC(d, af[0][0], bfr[0][0][ntp][so], bfr[0][0][ntp][so + 1]);
                MMA_ACC(d, af[0][1], bfr[0][1][ntp][so], bfr[0][1][ntp][so + 1]);
                acc[mt][nt][0] += d[0];
                acc[mt][nt][1] += d[1];
                acc[mt][nt][2] += d[2];
                acc[mt][nt][3] += d[3];
            }
        }
    }

    // ---- epilogue: Y (+bias) -> smem ys[w][col] ----
    __syncthreads();   // all MMA smem reads done; safe to overwrite stages
    float* ys = (float*)smem;
    const int q = lane & 3;
    const int r = lane >> 2;
#pragma unroll
    for (int nt = 0; nt < 4; ++nt) {
        const int col = (wn << 5) + (nt << 3) + (q << 1);
        const float2 bb = *(const float2*)&bias[n0 + col];
#pragma unroll
        for (int mt = 0; mt < 4; ++mt) {
            const int wrow = (wm << 6) + (mt << 4) + r;
            float2 v0, v1;
            v0.x = acc[mt][nt][0] + bb.x;
            v0.y = acc[mt][nt][1] + bb.y;
            v1.x = acc[mt][nt][2] + bb.x;
            v1.y = acc[mt][nt][3] + bb.y;
            *(float2*)&ys[wrow * YST + col]       = v0;
            *(float2*)&ys[(wrow + 8) * YST + col] = v1;
        }
    }
    __syncthreads();

    // ---- in-CTA bidirectional LIF scan: thread t < 128 owns e-column t ----
    if (tid < 128) {
        unsigned fw[4] = {0u, 0u, 0u, 0u};
        unsigned bw[4] = {0u, 0u, 0u, 0u};
        bool flag = false;
        float yv[32];

        {
            float v = 0.0f;
#pragma unroll
            for (int c = 0; c < 4; ++c) {
#pragma unroll
                for (int j = 0; j < 32; ++j)
                    yv[j] = ys[(c * 32 + j) * YST + tid];
#pragma unroll
                for (int j = 0; j < 32; ++j) {
                    const int w = c * 32 + j;
                    v = v + (yv[j] - v) * 0.5f;
                    flag |= (fabsf(v - 1.0f) < GUARD);
                    if (v - 1.0f >= 0.0f) {
                        fw[w >> 5] |= 1u << (w & 31);
                        v = 0.0f;
                    }
                }
            }
        }
        {
            float v = 0.0f;
#pragma unroll
            for (int c = 3; c >= 0; --c) {
#pragma unroll
                for (int j = 0; j < 32; ++j)
                    yv[j] = ys[(c * 32 + j) * YST + tid];
#pragma unroll
                for (int j = 31; j >= 0; --j) {
                    const int w = c * 32 + j;
                    v = v + (yv[j] - v) * 0.5f;
                    flag |= (fabsf(v - 1.0f) < GUARD);
                    if (v - 1.0f >= 0.0f) {
                        bw[w >> 5] |= 1u << (w & 31);
                        v = 0.0f;
                    }
                }
            }
        }

        float* op = out + ((size_t)(h * WD) * BB + b) * 512 + n0 + tid;
#pragma unroll
        for (int w = 0; w < WD; ++w) {
            float s = (float)(((fw[w >> 5] >> (w & 31)) & 1u) +
                              ((bw[w >> 5] >> (w & 31)) & 1u));
            op[(size_t)w * 4096] = s;
        }

        if (flag) {
            int idx = atomicAdd(&g_ecnt[hb], 1);
            if (idx < CAP) g_elist[hb][idx] = (unsigned short)(n0 + tid);
        }
    }
}

// ---------------------------------------------------------------------------
// Correction: one block per (h,b); recompute flagged e-columns exactly
// (ascending-k fp32 scalar FMA), redo both scans, overwrite out.
// ---------------------------------------------------------------------------
#define CSM_XS 0
#define CSM_WS (64 * 128)
#define CSM_YB (CSM_WS + 8 * 512)
#define CSM_TOTAL ((CSM_YB + 8 * 128) * 4)   // 53248 B

__global__ __launch_bounds__(256) void correct_kernel(
    const float* __restrict__ x,
    const float* __restrict__ Wl,
    const float* __restrict__ bias,
    float* __restrict__ out)
{
    extern __shared__ float csm[];
    float* xs   = csm + CSM_XS;
    float* ws   = csm + CSM_WS;
    float* ybuf = csm + CSM_YB;

    const int hb = blockIdx.x;
    int cnt = g_ecnt[hb];
    if (cnt <= 0) return;
    if (cnt > CAP) cnt = CAP;

    const int h = hb >> 3, b = hb & 7;
    const int tid = threadIdx.x, wrp = tid >> 5, lane = tid & 31;
    const size_t cbase = ((size_t)(h * WD) * BB + b) * DD;

    for (int ebase = 0; ebase < cnt; ebase += 8) {
        int e = -1;
        float be = 0.0f;
        if (ebase + wrp < cnt) {
            e = g_elist[hb][ebase + wrp];
            be = bias[e];
            const float4* wr = (const float4*)(Wl + (size_t)e * 512);
            float4* wd = (float4*)(ws + wrp * 512);
            for (int j = lane; j < 128; j += 32) wd[j] = wr[j];
        }

        float a0 = 0.f, a1 = 0.f, a2 = 0.f, a3 = 0.f;
        for (int ck = 0; ck < 8; ++ck) {
            __syncthreads();
#pragma unroll
            for (int i = 0; i < 2; ++i) {
                const int w = (tid >> 2) + i * 64;
                const float4* xr = (const float4*)(x + cbase +
                                                   (size_t)w * 4096 + ck * 64);
#pragma unroll
                for (int j = 0; j < 4; ++j) {
                    const int k4 = (tid & 3) + j * 4;
                    float4 v = xr[k4];
                    xs[(k4 * 4 + 0) * 128 + w] = v.x;
                    xs[(k4 * 4 + 1) * 128 + w] = v.y;
                    xs[(k4 * 4 + 2) * 128 + w] = v.z;
                    xs[(k4 * 4 + 3) * 128 + w] = v.w;
                }
            }
            __syncthreads();
            if (e >= 0) {
                const float* wc = ws + wrp * 512 + ck * 64;
                for (int kk = 0; kk < 64; ++kk) {
                    const float wv = wc[kk];
                    a0 = fmaf(xs[kk * 128 + lane],      wv, a0);
                    a1 = fmaf(xs[kk * 128 + lane + 32], wv, a1);
                    a2 = fmaf(xs[kk * 128 + lane + 64], wv, a2);
                    a3 = fmaf(xs[kk * 128 + lane + 96], wv, a3);
                }
            }
        }

        unsigned bits[4] = {0u, 0u, 0u, 0u};
        if (e >= 0) {
            ybuf[wrp * 128 + lane]      = a0 + be;
            ybuf[wrp * 128 + lane + 32] = a1 + be;
            ybuf[wrp * 128 + lane + 64] = a2 + be;
            ybuf[wrp * 128 + lane + 96] = a3 + be;
        }
        __syncwarp();
        if (e >= 0 && lane < 2) {
            float v = 0.0f;
            for (int i = 0; i < WD; ++i) {
                const int w = lane ? (WD - 1 - i) : i;
                float yt = ybuf[wrp * 128 + w];
                v = v + (yt - v) * 0.5f;
                if (v - 1.0f >= 0.0f) { bits[w >> 5] |= 1u << (w & 31); v = 0.0f; }
            }
        }
        unsigned fwv[4], bwv[4];
#pragma unroll
        for (int i = 0; i < 4; ++i) {
            fwv[i] = __shfl_sync(0xFFFFFFFFu, bits[i], 0);
            bwv[i] = __shfl_sync(0xFFFFFFFFu, bits[i], 1);
        }
        if (e >= 0) {
#pragma unroll
            for (int c = 0; c < 4; ++c) {
                const int w = lane + 32 * c;
                float s = (float)(((fwv[w >> 5] >> (w & 31)) & 1u) +
                                  ((bwv[w >> 5] >> (w & 31)) & 1u));
                out[cbase + (size_t)w * 4096 + e] = s;
            }
        }
        __syncthreads();
    }
}

extern "C" void kernel_launch(void* const* d_in, const int* in_sizes, int n_in,
                              void* d_out, int out_size)
{
    const float* x    = (const float*)d_in[0];   // (16384, 8, 512) fp32
    const float* Wlin = (const float*)d_in[1];   // (512, 512) fp32
    const float* blin = (const float*)d_in[2];   // (512,) fp32
    float* out = (float*)d_out;

    cudaFuncSetAttribute(gemm_scan_kernel,
                         cudaFuncAttributeMaxDynamicSharedMemorySize, SMEM_GEMM);
    cudaFuncSetAttribute(correct_kernel,
                         cudaFuncAttributeMaxDynamicSharedMemorySize, CSM_TOTAL);

    const int xblocks = (int)(X_ELEMS / 1024);
    const int wblocks = (int)(W_ELEMS / 1024);
    split_kernel<<<xblocks + wblocks, 256>>>(x, Wlin);

    dim3 ggrid(4, HH * BB);   // n-tiles x (h,b)
    gemm_scan_kernel<<<ggrid, 256, SMEM_GEMM>>>(blin, out);

    correct_kernel<<<HH * BB, 256, CSM_TOTAL>>>(x, Wlin, blin, out);
}

// round 16
// speedup vs baseline: 1.3834x; 1.0115x over previous
#include <cuda_runtime.h>
#include <cuda_fp16.h>
#include <cstdint>

// Problem dims
#define HH 128
#define WD 128
#define BB 8
#define DD 512
#define M_TOTAL (HH * WD * BB)   // 131072 rows
#define X_ELEMS ((size_t)M_TOTAL * DD)
#define W_ELEMS ((size_t)DD * DD)
#define GUARD 2e-5f
#define CAP 128

// Scratch
__device__ __half g_x0[X_ELEMS];
__device__ __half g_x1[X_ELEMS];
__device__ __half g_w0[W_ELEMS];
__device__ __half g_w1[W_ELEMS];
__device__ int g_ecnt[HH * BB];
__device__ unsigned short g_elist[HH * BB][CAP];

// ---------------------------------------------------------------------------
// MMA / LDSM / cp.async macros
// ---------------------------------------------------------------------------
#define MMA_ZERO(d, a, b0, b1)                                               \
    asm volatile(                                                            \
        "mma.sync.aligned.m16n8k16.row.col.f32.f16.f16.f32 "                \
        "{%0,%1,%2,%3}, {%4,%5,%6,%7}, {%8,%9}, {%10,%10,%10,%10};"         \
        : "=f"((d)[0]), "=f"((d)[1]), "=f"((d)[2]), "=f"((d)[3])             \
        : "r"((a)[0]), "r"((a)[1]), "r"((a)[2]), "r"((a)[3]),                \
          "r"(b0), "r"(b1), "f"(0.0f))

#define MMA_ACC(d, a, b0, b1)                                                \
    asm volatile(                                                            \
        "mma.sync.aligned.m16n8k16.row.col.f32.f16.f16.f32 "                \
        "{%0,%1,%2,%3}, {%4,%5,%6,%7}, {%8,%9}, {%0,%1,%2,%3};"             \
        : "+f"((d)[0]), "+f"((d)[1]), "+f"((d)[2]), "+f"((d)[3])             \
        : "r"((a)[0]), "r"((a)[1]), "r"((a)[2]), "r"((a)[3]),                \
          "r"(b0), "r"(b1))

#define LDSM_X4(r, addr)                                                     \
    asm volatile(                                                            \
        "ldmatrix.sync.aligned.m8n8.x4.shared.b16 {%0,%1,%2,%3}, [%4];"     \
        : "=r"((r)[0]), "=r"((r)[1]), "=r"((r)[2]), "=r"((r)[3])             \
        : "r"(addr))

#define CP_ASYNC(dst, src)                                                   \
    asm volatile("cp.async.cg.shared.global [%0], [%1], 16;"                \
                 :: "r"(dst), "l"(src) : "memory")
#define CP_COMMIT()  asm volatile("cp.async.commit_group;" ::: "memory")
#define CP_WAIT0()   asm volatile("cp.async.wait_group 0;" ::: "memory")

// SMEM geometry (uint32 units): [row 0..127][kp 0..15] stride 20.
// 4 arrays per stage (A0, A1, W0, W1), 2 stages. Epilogue reuses the region
// as float ys[128][132] (67584 B) + bit-exchange buffers (5120 B) <= 81920 B.
#define RST  20
#define ARR  (128 * RST)        // 2560 u32 = 10240 B
#define SSTG (4 * ARR)
#define SMEM_GEMM (2 * SSTG * 4)  // 81920 B
#define YST  132                  // ys row stride (floats)
#define BITS_OFF (128 * YST)      // float index where bitsbuf starts
#define FLAG_OFF (BITS_OFF + 256 * 4)

__device__ __forceinline__ uint32_t smem_u32(const void* p) {
    uint32_t a;
    asm("{ .reg .u64 t; cvta.to.shared.u64 t, %1; cvt.u32.u64 %0, t; }"
        : "=r"(a) : "l"(p));
    return a;
}

// ---------------------------------------------------------------------------
// Pre-split: fp32 -> fp16 hi/lo
// ---------------------------------------------------------------------------
__global__ __launch_bounds__(256) void split_kernel(
    const float* __restrict__ x, const float* __restrict__ w)
{
    const int tid = threadIdx.x;
    if (blockIdx.x == 0) {
        for (int i = tid; i < HH * BB; i += 256) g_ecnt[i] = 0;
    }
    size_t i4 = ((size_t)blockIdx.x * 256 + tid) * 4;
    const float* src;
    __half *d0, *d1;
    if (i4 < X_ELEMS) {
        src = x + i4; d0 = g_x0 + i4; d1 = g_x1 + i4;
    } else {
        i4 -= X_ELEMS;
        if (i4 >= W_ELEMS) return;
        src = w + i4; d0 = g_w0 + i4; d1 = g_w1 + i4;
    }
    float4 v = *(const float4*)src;
    const float f[4] = {v.x, v.y, v.z, v.w};
    unsigned short h[4], l[4];
#pragma unroll
    for (int j = 0; j < 4; ++j) {
        __half hh = __float2half_rn(f[j]);
        __half ll = __float2half_rn(f[j] - __half2float(hh));
        h[j] = __half_as_ushort(hh);
        l[j] = __half_as_ushort(ll);
    }
    *(uint2*)d0 = make_uint2((uint32_t)h[0] | ((uint32_t)h[1] << 16),
                             (uint32_t)h[2] | ((uint32_t)h[3] << 16));
    *(uint2*)d1 = make_uint2((uint32_t)l[0] | ((uint32_t)l[1] << 16),
                             (uint32_t)l[2] | ((uint32_t)l[3] << 16));
}

// ---------------------------------------------------------------------------
// Fused GEMM + scan: CTA tile = 128 w-rows of one (h,b) x 128 e-cols.
// GEMM core frozen from R11. Epilogue: Y -> smem; threads 0-127 run FORWARD
// scans, threads 128-255 run BACKWARD scans concurrently; masks exchanged
// via smem; both halves split the output stores. Flagging unchanged.
// ---------------------------------------------------------------------------
__global__ __launch_bounds__(256, 2) void gemm_scan_kernel(
    const float* __restrict__ bias,
    float* __restrict__ out)
{
    extern __shared__ uint32_t smem[];
    const uint32_t sb = smem_u32(smem);

    const int tid  = threadIdx.x;
    const int lane = tid & 31;
    const int wid  = tid >> 5;
    const int wm   = wid >> 2;        // 0..1
    const int wn   = wid & 3;         // 0..3

    const int hb = blockIdx.y;        // h*8 + b
    const int h  = hb >> 3;
    const int b  = hb & 7;
    const int n0 = blockIdx.x << 7;

    // producer: w-row = tid>>1; global X row = (h*128 + w)*8 + b
    const int prow  = tid >> 1;
    const int cpair = (tid & 1) << 1;
    const size_t xrow = ((size_t)(h * WD + prow) * BB + b) * 512 + cpair * 8;
    const __half* src[4];
    src[0] = g_x0 + xrow;
    src[1] = g_x1 + xrow;
    src[2] = g_w0 + (size_t)(n0 + prow) * 512 + cpair * 8;
    src[3] = g_w1 + (size_t)(n0 + prow) * 512 + cpair * 8;
    const uint32_t dstb = sb + 4 * (prow * RST + cpair * 4);

    const uint32_t a_off = ((wm << 6) + (lane & 15)) * RST + ((lane >> 4) << 2);
    const uint32_t b_off = ((wn << 5) + ((lane >> 4) << 3) + (lane & 7)) * RST +
                           (((lane >> 3) & 1) << 2);

    float acc[4][4][4];
#pragma unroll
    for (int mt = 0; mt < 4; ++mt)
#pragma unroll
        for (int nt = 0; nt < 4; ++nt)
#pragma unroll
            for (int r = 0; r < 4; ++r) acc[mt][nt][r] = 0.0f;

#pragma unroll
    for (int arr = 0; arr < 4; ++arr) {
#pragma unroll
        for (int c = 0; c < 2; ++c)
            CP_ASYNC(dstb + 4 * (arr * ARR) + c * 16, src[arr] + c * 8);
    }
    CP_COMMIT();

    for (int it = 0; it < 16; ++it) {
        const uint32_t stg = (it & 1) ? (uint32_t)SSTG : 0u;

        CP_WAIT0();
        __syncthreads();

        if (it < 15) {
            const uint32_t nst = (it & 1) ? 0u : (uint32_t)SSTG;
            const int koff = (it + 1) * 32;
#pragma unroll
            for (int arr = 0; arr < 4; ++arr) {
#pragma unroll
                for (int c = 0; c < 2; ++c)
                    CP_ASYNC(dstb + 4 * (nst + arr * ARR) + c * 16,
                             src[arr] + koff + c * 8);
            }
            CP_COMMIT();
        }

        uint32_t bfr[2][2][2][4];
#pragma unroll
        for (int lvl = 0; lvl < 2; ++lvl)
#pragma unroll
            for (int ks = 0; ks < 2; ++ks)
#pragma unroll
                for (int ntp = 0; ntp < 2; ++ntp) {
                    const uint32_t addr = sb + 4 * (stg + (2 + lvl) * ARR +
                                                    b_off + ks * 8 + ntp * 320);
                    LDSM_X4(bfr[lvl][ks][ntp], addr);
                }

#pragma unroll
        for (int mt = 0; mt < 4; ++mt) {
            uint32_t af[2][2][4];
#pragma unroll
            for (int lvl = 0; lvl < 2; ++lvl)
#pragma unroll
                for (int ks = 0; ks < 2; ++ks) {
                    const uint32_t addr = sb + 4 * (stg + lvl * ARR + a_off +
                                                    ks * 8 + mt * 320);
                    LDSM_X4(af[lvl][ks], addr);
                }
#pragma unroll
            for (int nt = 0; nt < 4; ++nt) {
                const int ntp = nt >> 1, so = (nt & 1) << 1;
                float d[4];
                MMA_ZERO(d, af[1][0], bfr[0][0][ntp][so], bfr[0][0][ntp][so + 1]);
                MMA_ACC(d, af[1][1], bfr[0][1][ntp][so], bfr[0][1][ntp][so + 1]);
                MMA_ACC(d, af[0][0], bfr[1][0][ntp][so], bfr[1][0][ntp][so + 1]);
                MMA_ACC(d, af[0][1], bfr[1][1][ntp][so], bfr[1][1][ntp][so + 1]);
                MMA_ACC(d, af[0][0], bfr[0][0][ntp][so], bfr[0][0][ntp][so + 1]);
                MMA_ACC(d, af[0][1], bfr[0][1][ntp][so], bfr[0][1][ntp][so + 1]);
                acc[mt][nt][0] += d[0];
                acc[mt][nt][1] += d[1];
                acc[mt][nt][2] += d[2];
                acc[mt][nt][3] += d[3];
            }
        }
    }

    // ---- epilogue: Y (+bias) -> smem ys[w][col] ----
    __syncthreads();   // all MMA smem reads done; safe to overwrite stages
    float* ys = (float*)smem;
    unsigned* bitsbuf = (unsigned*)smem + BITS_OFF;   // [256][4]
    int* flagbuf = (int*)smem + FLAG_OFF;             // [256]
    const int q = lane & 3;
    const int r = lane >> 2;
#pragma unroll
    for (int nt = 0; nt < 4; ++nt) {
        const int col = (wn << 5) + (nt << 3) + (q << 1);
        const float2 bb = *(const float2*)&bias[n0 + col];
#pragma unroll
        for (int mt = 0; mt < 4; ++mt) {
            const int wrow = (wm << 6) + (mt << 4) + r;
            float2 v0, v1;
            v0.x = acc[mt][nt][0] + bb.x;
            v0.y = acc[mt][nt][1] + bb.y;
            v1.x = acc[mt][nt][2] + bb.x;
            v1.y = acc[mt][nt][3] + bb.y;
            *(float2*)&ys[wrow * YST + col]       = v0;
            *(float2*)&ys[(wrow + 8) * YST + col] = v1;
        }
    }
    __syncthreads();

    // ---- parallel bidirectional scan: lower half fwd, upper half bwd ----
    {
        const int col = tid & 127;
        const bool bwd = tid >= 128;
        unsigned bits[4] = {0u, 0u, 0u, 0u};
        bool flag = false;
        float yv[32];
        float v = 0.0f;

        if (!bwd) {
#pragma unroll
            for (int c = 0; c < 4; ++c) {
#pragma unroll
                for (int j = 0; j < 32; ++j)
                    yv[j] = ys[(c * 32 + j) * YST + col];
#pragma unroll
                for (int j = 0; j < 32; ++j) {
                    const int w = c * 32 + j;
                    v = v + (yv[j] - v) * 0.5f;
                    flag |= (fabsf(v - 1.0f) < GUARD);
                    if (v - 1.0f >= 0.0f) {
                        bits[w >> 5] |= 1u << (w & 31);
                        v = 0.0f;
                    }
                }
            }
        } else {
#pragma unroll
            for (int c = 3; c >= 0; --c) {
#pragma unroll
                for (int j = 0; j < 32; ++j)
                    yv[j] = ys[(c * 32 + j) * YST + col];
#pragma unroll
                for (int j = 31; j >= 0; --j) {
                    const int w = c * 32 + j;
                    v = v + (yv[j] - v) * 0.5f;
                    flag |= (fabsf(v - 1.0f) < GUARD);
                    if (v - 1.0f >= 0.0f) {
                        bits[w >> 5] |= 1u << (w & 31);
                        v = 0.0f;
                    }
                }
            }
        }

#pragma unroll
        for (int i = 0; i < 4; ++i) bitsbuf[tid * 4 + i] = bits[i];
        flagbuf[tid] = flag ? 1 : 0;
        __syncthreads();

        // combine: thread t<128 writes w 0..63; thread t>=128 writes w 64..127
        unsigned fwv[4], bwv[4];
        if (!bwd) {
#pragma unroll
            for (int i = 0; i < 4; ++i) {
                fwv[i] = bits[i];
                bwv[i] = bitsbuf[(col + 128) * 4 + i];
            }
        } else {
#pragma unroll
            for (int i = 0; i < 4; ++i) {
                fwv[i] = bitsbuf[col * 4 + i];
                bwv[i] = bits[i];
            }
        }

        float* op = out + ((size_t)(h * WD) * BB + b) * 512 + n0 + col;
        const int w0 = bwd ? 64 : 0;
#pragma unroll
        for (int j = 0; j < 64; ++j) {
            const int w = w0 + j;
            float s = (float)(((fwv[w >> 5] >> (w & 31)) & 1u) +
                              ((bwv[w >> 5] >> (w & 31)) & 1u));
            op[(size_t)w * 4096] = s;
        }

        if (!bwd && (flag || flagbuf[col + 128])) {
            int idx = atomicAdd(&g_ecnt[hb], 1);
            if (idx < CAP) g_elist[hb][idx] = (unsigned short)(n0 + col);
        }
    }
}

// ---------------------------------------------------------------------------
// Correction: one block per (h,b); recompute flagged e-columns exactly
// (ascending-k fp32 scalar FMA), redo both scans, overwrite out.
// ---------------------------------------------------------------------------
#define CSM_XS 0
#define CSM_WS (64 * 128)
#define CSM_YB (CSM_WS + 8 * 512)
#define CSM_TOTAL ((CSM_YB + 8 * 128) * 4)   // 53248 B

__global__ __launch_bounds__(256) void correct_kernel(
    const float* __restrict__ x,
    const float* __restrict__ Wl,
    const float* __restrict__ bias,
    float* __restrict__ out)
{
    extern __shared__ float csm[];
    float* xs   = csm + CSM_XS;
    float* ws   = csm + CSM_WS;
    float* ybuf = csm + CSM_YB;

    const int hb = blockIdx.x;
    int cnt = g_ecnt[hb];
    if (cnt <= 0) return;
    if (cnt > CAP) cnt = CAP;

    const int h = hb >> 3, b = hb & 7;
    const int tid = threadIdx.x, wrp = tid >> 5, lane = tid & 31;
    const size_t cbase = ((size_t)(h * WD) * BB + b) * DD;

    for (int ebase = 0; ebase < cnt; ebase += 8) {
        int e = -1;
        float be = 0.0f;
        if (ebase + wrp < cnt) {
            e = g_elist[hb][ebase + wrp];
            be = bias[e];
            const float4* wr = (const float4*)(Wl + (size_t)e * 512);
            float4* wd = (float4*)(ws + wrp * 512);
            for (int j = lane; j < 128; j += 32) wd[j] = wr[j];
        }

        float a0 = 0.f, a1 = 0.f, a2 = 0.f, a3 = 0.f;
        for (int ck = 0; ck < 8; ++ck) {
            __syncthreads();
#pragma unroll
            for (int i = 0; i < 2; ++i) {
                const int w = (tid >> 2) + i * 64;
                const float4* xr = (const float4*)(x + cbase +
                                                   (size_t)w * 4096 + ck * 64);
#pragma unroll
                for (int j = 0; j < 4; ++j) {
                    const int k4 = (tid & 3) + j * 4;
                    float4 v = xr[k4];
                    xs[(k4 * 4 + 0) * 128 + w] = v.x;
                    xs[(k4 * 4 + 1) * 128 + w] = v.y;
                    xs[(k4 * 4 + 2) * 128 + w] = v.z;
                    xs[(k4 * 4 + 3) * 128 + w] = v.w;
                }
            }
            __syncthreads();
            if (e >= 0) {
                const float* wc = ws + wrp * 512 + ck * 64;
                for (int kk = 0; kk < 64; ++kk) {
                    const float wv = wc[kk];
                    a0 = fmaf(xs[kk * 128 + lane],      wv, a0);
                    a1 = fmaf(xs[kk * 128 + lane + 32], wv, a1);
                    a2 = fmaf(xs[kk * 128 + lane + 64], wv, a2);
                    a3 = fmaf(xs[kk * 128 + lane + 96], wv, a3);
                }
            }
        }

        unsigned bits[4] = {0u, 0u, 0u, 0u};
        if (e >= 0) {
            ybuf[wrp * 128 + lane]      = a0 + be;
            ybuf[wrp * 128 + lane + 32] = a1 + be;
            ybuf[wrp * 128 + lane + 64] = a2 + be;
            ybuf[wrp * 128 + lane + 96] = a3 + be;
        }
        __syncwarp();
        if (e >= 0 && lane < 2) {
            float v = 0.0f;
            for (int i = 0; i < WD; ++i) {
                const int w = lane ? (WD - 1 - i) : i;
                float yt = ybuf[wrp * 128 + w];
                v = v + (yt - v) * 0.5f;
                if (v - 1.0f >= 0.0f) { bits[w >> 5] |= 1u << (w & 31); v = 0.0f; }
            }
        }
        unsigned fwv[4], bwv[4];
#pragma unroll
        for (int i = 0; i < 4; ++i) {
            fwv[i] = __shfl_sync(0xFFFFFFFFu, bits[i], 0);
            bwv[i] = __shfl_sync(0xFFFFFFFFu, bits[i], 1);
        }
        if (e >= 0) {
#pragma unroll
            for (int c = 0; c < 4; ++c) {
                const int w = lane + 32 * c;
                float s = (float)(((fwv[w >> 5] >> (w & 31)) & 1u) +
                                  ((bwv[w >> 5] >> (w & 31)) & 1u));
                out[cbase + (size_t)w * 4096 + e] = s;
            }
        }
        __syncthreads();
    }
}

extern "C" void kernel_launch(void* const* d_in, const int* in_sizes, int n_in,
                              void* d_out, int out_size)
{
    const float* x    = (const float*)d_in[0];   // (16384, 8, 512) fp32
    const float* Wlin = (const float*)d_in[1];   // (512, 512) fp32
    const float* blin = (const float*)d_in[2];   // (512,) fp32
    float* out = (float*)d_out;

    cudaFuncSetAttribute(gemm_scan_kernel,
                         cudaFuncAttributeMaxDynamicSharedMemorySize, SMEM_GEMM);
    cudaFuncSetAttribute(correct_kernel,
                         cudaFuncAttributeMaxDynamicSharedMemorySize, CSM_TOTAL);

    const int xblocks = (int)(X_ELEMS / 1024);
    const int wblocks = (int)(W_ELEMS / 1024);
    split_kernel<<<xblocks + wblocks, 256>>>(x, Wlin);

    dim3 ggrid(4, HH * BB);   // n-tiles x (h,b)
    gemm_scan_kernel<<<ggrid, 256, SMEM_GEMM>>>(blin, out);

    correct_kernel<<<HH * BB, 256, CSM_TOTAL>>>(x, Wlin, blin, out);
}